// round 2
// baseline (speedup 1.0000x reference)
#include <cuda_runtime.h>
#include <cuda_bf16.h>

// Problem constants
#define LSEQ  1024
#define BATCH 16
#define DIN   1024
#define NOUT  512
#define NLAY  4
#define MROWS (LSEQ*BATCH)   // 16384
#define KDIM  1024
#define NDIM  3072           // 6 * NOUT

// Scratch (device globals: allocation-free)
__device__ float g_x0[MROWS * DIN];   // 64 MB
__device__ float g_x1[MROWS * DIN];   // 64 MB
__device__ float g_u [MROWS * NDIM];  // 192 MB

// ---------------------------------------------------------------------------
// Embedding gather: x0[(l*B+b), d] = emb[token[l*B+b], d]   (float4 vectorized)
// ---------------------------------------------------------------------------
__global__ void gather_kernel(const int* __restrict__ tok,
                              const float* __restrict__ emb,
                              float* __restrict__ out) {
    int e = blockIdx.x * blockDim.x + threadIdx.x;   // float4 index, total MROWS*DIN/4
    int row = e >> 8;          // / (DIN/4=256)
    int d4  = e & 255;
    int t = tok[row];
    reinterpret_cast<float4*>(out)[e] =
        reinterpret_cast<const float4*>(emb + (size_t)t * DIN)[d4];
}

// ---------------------------------------------------------------------------
// SGEMM: U = X(M,K) * W(K,N), fused bias+sigmoid on gate columns.
// 128x128 tile, BK=8, 256 threads, 8x8 per-thread register tile.
// Column semantics within NDIM=3072: per dir (1536 cols):
//   [0,512) xt (raw), [512,1024) f-gate -> sigmoid(v+bf), [1024,1536) r-gate -> sigmoid(v+br)
// bias layout: bs_l[0..1024) = bf (dir0,dir1), bs_l[1024..2048) = br
// ---------------------------------------------------------------------------
__global__ void sgemm_act_kernel(const float* __restrict__ A,
                                 const float* __restrict__ W,
                                 const float* __restrict__ bias,
                                 float* __restrict__ U) {
    __shared__ float As[8][128];
    __shared__ float Bs[8][128];

    const int tid = threadIdx.x;
    const int tx = tid & 15;          // 0..15 -> col group
    const int ty = tid >> 4;          // 0..15 -> row group
    const int rowBase = blockIdx.y * 128;
    const int colBase = blockIdx.x * 128;

    // A-tile load mapping: 128 rows x 8 k, 2 float4 per row (along k)
    const int aRow = tid >> 1;              // 0..127
    const int aK4  = (tid & 1) * 4;         // 0 or 4
    // B-tile load mapping: 8 k x 128 n, float4 along n
    const int bK  = tid >> 5;               // 0..7
    const int bN4 = (tid & 31) * 4;         // 0..124

    const float* Aptr = A + (size_t)(rowBase + aRow) * KDIM + aK4;
    const float* Bptr = W + (size_t)bK * NDIM + colBase + bN4;

    float acc[8][8];
    #pragma unroll
    for (int i = 0; i < 8; i++)
        #pragma unroll
        for (int j = 0; j < 8; j++) acc[i][j] = 0.f;

    for (int k0 = 0; k0 < KDIM; k0 += 8) {
        float4 av = *reinterpret_cast<const float4*>(Aptr); Aptr += 8;
        float4 bv = *reinterpret_cast<const float4*>(Bptr); Bptr += (size_t)8 * NDIM;

        As[aK4 + 0][aRow] = av.x;
        As[aK4 + 1][aRow] = av.y;
        As[aK4 + 2][aRow] = av.z;
        As[aK4 + 3][aRow] = av.w;
        *reinterpret_cast<float4*>(&Bs[bK][bN4]) = bv;
        __syncthreads();

        #pragma unroll
        for (int k = 0; k < 8; k++) {
            float a[8], b[8];
            #pragma unroll
            for (int i = 0; i < 8; i++) a[i] = As[k][ty * 8 + i];
            #pragma unroll
            for (int j = 0; j < 8; j++) b[j] = Bs[k][tx * 8 + j];
            #pragma unroll
            for (int i = 0; i < 8; i++)
                #pragma unroll
                for (int j = 0; j < 8; j++)
                    acc[i][j] = fmaf(a[i], b[j], acc[i][j]);
        }
        __syncthreads();
    }

    // Epilogue: the 8-wide col group never crosses a 512 boundary (8 | 512).
    const int colG = colBase + tx * 8;
    const int dir  = colG / 1536;
    const int cm   = colG % 1536;
    int btype = 0;                 // 0 = raw xt, 1 = f-gate, 2 = r-gate
    float bvals[8];
    if (cm >= 1024)      btype = 2;
    else if (cm >= 512)  btype = 1;
    if (btype == 1) {
        #pragma unroll
        for (int j = 0; j < 8; j++) bvals[j] = bias[dir * 512 + (cm - 512) + j];
    } else if (btype == 2) {
        #pragma unroll
        for (int j = 0; j < 8; j++) bvals[j] = bias[1024 + dir * 512 + (cm - 1024) + j];
    }

    #pragma unroll
    for (int i = 0; i < 8; i++) {
        const int row = rowBase + ty * 8 + i;
        float* up = U + (size_t)row * NDIM + colG;
        #pragma unroll
        for (int j = 0; j < 8; j++) {
            float v = acc[i][j];
            if (btype != 0) v = 1.f / (1.f + __expf(-(v + bvals[j])));
            up[j] = v;
        }
    }
}

// ---------------------------------------------------------------------------
// SRU scan: one thread per (dir, b, i) chain; f/r already sigmoided in U.
//   c = f*c + (1-f)*xt ;  h = r*tanh(c) + (1-r)*xp
// dir0 forward over l, dir1 backward; h written at original l positions.
// Final c -> Cout[b*1024 + dir*512 + i].
// ---------------------------------------------------------------------------
__global__ void scan_kernel(const float* __restrict__ U,
                            const float* __restrict__ Xin,
                            float* __restrict__ Xout,
                            float* __restrict__ Cout) {
    const int idx = blockIdx.x * blockDim.x + threadIdx.x;   // 0..16383
    const int dir = idx >> 13;
    const int bi  = idx & 8191;
    const int b   = bi >> 9;
    const int i   = bi & 511;

    const float* u0 = U   + (size_t)b * NDIM + dir * 1536 + i;
    const float* x0 = Xin + (size_t)b * DIN  + dir * 512  + i;
    float*       h0 = Xout + (size_t)b * DIN + dir * 512  + i;
    const int ustep = BATCH * NDIM;   // 49152
    const int xstep = BATCH * DIN;    // 16384

    float c = 0.f;
    if (dir == 0) {
        #pragma unroll 4
        for (int l = 0; l < LSEQ; l++) {
            const float* up = u0 + (size_t)l * ustep;
            float xt = up[0];
            float f  = up[512];
            float r  = up[1024];
            float xp = x0[(size_t)l * xstep];
            c = f * c + (1.f - f) * xt;
            float h = r * tanhf(c) + (1.f - r) * xp;
            h0[(size_t)l * xstep] = h;
        }
    } else {
        #pragma unroll 4
        for (int l = LSEQ - 1; l >= 0; l--) {
            const float* up = u0 + (size_t)l * ustep;
            float xt = up[0];
            float f  = up[512];
            float r  = up[1024];
            float xp = x0[(size_t)l * xstep];
            c = f * c + (1.f - f) * xt;
            float h = r * tanhf(c) + (1.f - r) * xp;
            h0[(size_t)l * xstep] = h;
        }
    }
    Cout[b * 1024 + dir * 512 + i] = c;
}

// ---------------------------------------------------------------------------
// Launch
// inputs: [0] rnn_input int32 (L,B)  [1] input_lengths (unused)
//         [2] emb f32 (32000,1024)   [3] Ws f32 (4,1024,3072)  [4] bs f32 (4,2048)
// output: x (L,B,1024) flattened, then hidden (4,16,1024) flattened
// ---------------------------------------------------------------------------
extern "C" void kernel_launch(void* const* d_in, const int* in_sizes, int n_in,
                              void* d_out, int out_size) {
    const int*   tok = (const int*)d_in[0];
    const float* emb = (const float*)d_in[2];
    const float* Ws  = (const float*)d_in[3];
    const float* bs  = (const float*)d_in[4];
    float* out = (float*)d_out;

    float *x0, *x1, *u;
    cudaGetSymbolAddress((void**)&x0, g_x0);
    cudaGetSymbolAddress((void**)&x1, g_x1);
    cudaGetSymbolAddress((void**)&u,  g_u);

    // 1) embedding gather
    gather_kernel<<<(MROWS * DIN / 4) / 256, 256>>>(tok, emb, x0);

    float* xcur = x0;
    float* xalt = x1;
    float* xout_base = out;                           // x region: 16,777,216 floats
    float* hid_base  = out + (size_t)MROWS * DIN;     // hidden region: 4*16*1024

    dim3 ggrid(NDIM / 128, MROWS / 128);              // (24, 128)
    for (int l = 0; l < NLAY; l++) {
        const float* Wl = Ws + (size_t)l * KDIM * NDIM;
        const float* bl = bs + (size_t)l * 2048;
        sgemm_act_kernel<<<ggrid, 256>>>(xcur, Wl, bl, u);

        float* xnext = (l == NLAY - 1) ? xout_base : xalt;
        scan_kernel<<<128, 128>>>(u, xcur, xnext, hid_base + (size_t)l * BATCH * DIN);

        float* tmp = xcur; xcur = xalt; xalt = tmp;
        xcur = xnext;   // (for l==3 this is d_out; loop ends)
    }
}

// round 3
// speedup vs baseline: 2.6095x; 2.6095x over previous
#include <cuda_runtime.h>
#include <cuda_bf16.h>

// Problem constants
#define LSEQ  1024
#define BATCH 16
#define DIN   1024
#define NOUT  512
#define NLAY  4
#define MROWS (LSEQ*BATCH)   // 16384
#define KDIM  1024
#define NDIM  3072           // 6 * NOUT

// Scratch (device globals: allocation-free)
__device__ float g_x0[MROWS * DIN];   // 64 MB
__device__ float g_x1[MROWS * DIN];   // 64 MB
__device__ float g_u [MROWS * NDIM];  // 192 MB

// ---------------------------------------------------------------------------
// Embedding gather (float4 vectorized)
// ---------------------------------------------------------------------------
__global__ void gather_kernel(const int* __restrict__ tok,
                              const float* __restrict__ emb,
                              float* __restrict__ out) {
    int e = blockIdx.x * blockDim.x + threadIdx.x;
    int row = e >> 8;          // / (DIN/4=256)
    int d4  = e & 255;
    int t = tok[row];
    reinterpret_cast<float4*>(out)[e] =
        reinterpret_cast<const float4*>(emb + (size_t)t * DIN)[d4];
}

// ---------------------------------------------------------------------------
// TF32 tensor-core GEMM: U = X(M,K) * W(K,N), fused bias+sigmoid on gates.
// Block 128x128, BK=16, 256 threads (8 warps as 2x4, warp tile 64x32).
// mma.sync.m16n8k8 tf32. Double-buffered smem, register prefetch.
// ---------------------------------------------------------------------------
__device__ __forceinline__ unsigned f2tf32(float x) {
    unsigned r;
    asm("cvt.rna.tf32.f32 %0, %1;" : "=r"(r) : "f"(x));
    return r;
}

__device__ __forceinline__ void mma_tf32(float c[4],
                                         unsigned a0, unsigned a1, unsigned a2, unsigned a3,
                                         unsigned b0, unsigned b1) {
    asm volatile(
        "mma.sync.aligned.m16n8k8.row.col.f32.tf32.tf32.f32 "
        "{%0,%1,%2,%3}, {%4,%5,%6,%7}, {%8,%9}, {%0,%1,%2,%3};"
        : "+f"(c[0]), "+f"(c[1]), "+f"(c[2]), "+f"(c[3])
        : "r"(a0), "r"(a1), "r"(a2), "r"(a3), "r"(b0), "r"(b1));
}

// smem layouts (per buffer):
//  A: pair layout, plane per kstep s (s=0,1):
//     As[s*1032 + row*8 + j*2 + half] = A[row][8s + j + 4*half]   (j=0..3)
//     -> one LDS.64 yields (a_k, a_{k+4}) for a row.
//  B: plain [k][n], row stride 136 floats (conflict-free for STS.128 + LDS.32)
#define A_PLANE 1032
#define B_STRIDE 136

__global__ void __launch_bounds__(256)
gemm_tf32_kernel(const float* __restrict__ A,
                 const float* __restrict__ W,
                 const float* __restrict__ bias,
                 float* __restrict__ U) {
    __shared__ float As[2][2 * A_PLANE];     // 16.5 KB
    __shared__ float Bs[2][16 * B_STRIDE];   // 17.4 KB

    const int tid  = threadIdx.x;
    const int lane = tid & 31;
    const int warp = tid >> 5;
    const int wm = warp >> 2;        // 0..1
    const int wn = warp & 3;         // 0..3
    const int rowBase = blockIdx.y * 128;
    const int colBase = blockIdx.x * 128;

    // global load mapping
    const int ar = tid >> 2;         // 0..63  (A row; +64 for p=1)
    const int ac = tid & 3;          // float4 index along k (16 floats)
    const int br = tid >> 5;         // 0..7   (B k-row; +8 for p=1)
    const int bc = tid & 31;         // float4 index along n

    const float* Ag = A + (size_t)(rowBase + ar) * KDIM + ac * 4;
    const float* Bg = W + (size_t)br * NDIM + colBase + bc * 4;

    float4 pa[2], pb[2];
    pa[0] = *reinterpret_cast<const float4*>(Ag);
    pa[1] = *reinterpret_cast<const float4*>(Ag + (size_t)64 * KDIM);
    pb[0] = *reinterpret_cast<const float4*>(Bg);
    pb[1] = *reinterpret_cast<const float4*>(Bg + (size_t)8 * NDIM);

    float acc[4][4][4];
    #pragma unroll
    for (int mf = 0; mf < 4; mf++)
        #pragma unroll
        for (int nf = 0; nf < 4; nf++)
            #pragma unroll
            for (int e = 0; e < 4; e++) acc[mf][nf][e] = 0.f;

    const int a_s    = ac >> 1;      // kstep plane
    const int a_half = ac & 1;

    // stage prefetched regs -> smem buffer
    auto stage = [&](int buf) {
        #pragma unroll
        for (int p = 0; p < 2; p++) {
            int r = ar + 64 * p;
            float v[4] = {pa[p].x, pa[p].y, pa[p].z, pa[p].w};
            float* dst = &As[buf][a_s * A_PLANE + r * 8 + a_half];
            #pragma unroll
            for (int e = 0; e < 4; e++)
                dst[e * 2] = __uint_as_float(f2tf32(v[e]));
        }
        #pragma unroll
        for (int p = 0; p < 2; p++) {
            int k = br + 8 * p;
            float4 cv;
            cv.x = __uint_as_float(f2tf32(p == 0 ? pb[0].x : pb[1].x));
            cv.y = __uint_as_float(f2tf32(p == 0 ? pb[0].y : pb[1].y));
            cv.z = __uint_as_float(f2tf32(p == 0 ? pb[0].z : pb[1].z));
            cv.w = __uint_as_float(f2tf32(p == 0 ? pb[0].w : pb[1].w));
            *reinterpret_cast<float4*>(&Bs[buf][k * B_STRIDE + bc * 4]) = cv;
        }
    };

    stage(0);
    __syncthreads();

    const int q = lane >> 2;     // 0..7
    const int j = lane & 3;      // 0..3
    int buf = 0;

    for (int it = 0; it < 64; it++) {
        if (it < 63) {
            const float* Ag2 = Ag + (it + 1) * 16;
            const float* Bg2 = Bg + (size_t)(it + 1) * 16 * NDIM;
            pa[0] = *reinterpret_cast<const float4*>(Ag2);
            pa[1] = *reinterpret_cast<const float4*>(Ag2 + (size_t)64 * KDIM);
            pb[0] = *reinterpret_cast<const float4*>(Bg2);
            pb[1] = *reinterpret_cast<const float4*>(Bg2 + (size_t)8 * NDIM);
        }

        #pragma unroll
        for (int s = 0; s < 2; s++) {
            float2 alo[4], ahi[4];
            #pragma unroll
            for (int mf = 0; mf < 4; mf++) {
                int r = wm * 64 + mf * 16 + q;
                alo[mf] = *reinterpret_cast<const float2*>(
                    &As[buf][s * A_PLANE + r * 8 + j * 2]);
                ahi[mf] = *reinterpret_cast<const float2*>(
                    &As[buf][s * A_PLANE + (r + 8) * 8 + j * 2]);
            }
            float b0[4], b1[4];
            #pragma unroll
            for (int nf = 0; nf < 4; nf++) {
                int n = wn * 32 + nf * 8 + q;
                b0[nf] = Bs[buf][(s * 8 + j) * B_STRIDE + n];
                b1[nf] = Bs[buf][(s * 8 + j + 4) * B_STRIDE + n];
            }
            #pragma unroll
            for (int mf = 0; mf < 4; mf++)
                #pragma unroll
                for (int nf = 0; nf < 4; nf++)
                    mma_tf32(acc[mf][nf],
                             __float_as_uint(alo[mf].x), __float_as_uint(ahi[mf].x),
                             __float_as_uint(alo[mf].y), __float_as_uint(ahi[mf].y),
                             __float_as_uint(b0[nf]),    __float_as_uint(b1[nf]));
        }

        if (it < 63) {
            stage(buf ^ 1);
            __syncthreads();
            buf ^= 1;
        }
    }

    // -------- Epilogue: bias + sigmoid on gate columns, float2 stores --------
    // Warp's 32-col slice lies within one 512-col block (gate type uniform).
    const int wcol = colBase + wn * 32;          // warp col base
    const int dir  = wcol / 1536;
    const int cm   = wcol - dir * 1536;
    int btype = 0;
    const float* bptr = bias;
    if (cm >= 1024)      { btype = 2; bptr = bias + 1024 + dir * 512 + (cm - 1024); }
    else if (cm >= 512)  { btype = 1; bptr = bias + dir * 512 + (cm - 512); }

    #pragma unroll
    for (int nf = 0; nf < 4; nf++) {
        const int coff = nf * 8 + 2 * j;       // within warp slice
        float bv0 = 0.f, bv1 = 0.f;
        if (btype) { bv0 = bptr[coff]; bv1 = bptr[coff + 1]; }
        const int col = wcol + coff;
        #pragma unroll
        for (int mf = 0; mf < 4; mf++) {
            const int row0 = rowBase + wm * 64 + mf * 16 + q;
            float v0 = acc[mf][nf][0], v1 = acc[mf][nf][1];
            float v2 = acc[mf][nf][2], v3 = acc[mf][nf][3];
            if (btype) {
                v0 = 1.f / (1.f + __expf(-(v0 + bv0)));
                v1 = 1.f / (1.f + __expf(-(v1 + bv1)));
                v2 = 1.f / (1.f + __expf(-(v2 + bv0)));
                v3 = 1.f / (1.f + __expf(-(v3 + bv1)));
            }
            *reinterpret_cast<float2*>(&U[(size_t)row0 * NDIM + col])
                = make_float2(v0, v1);
            *reinterpret_cast<float2*>(&U[(size_t)(row0 + 8) * NDIM + col])
                = make_float2(v2, v3);
        }
    }
}

// ---------------------------------------------------------------------------
// SRU scan: one thread per (dir, b, i) chain; f/r already sigmoided in U.
// ---------------------------------------------------------------------------
__device__ __forceinline__ float tanh_fast(float x) {
    float y;
    asm("tanh.approx.f32 %0, %1;" : "=f"(y) : "f"(x));
    return y;
}

__global__ void scan_kernel(const float* __restrict__ U,
                            const float* __restrict__ Xin,
                            float* __restrict__ Xout,
                            float* __restrict__ Cout) {
    const int idx = blockIdx.x * blockDim.x + threadIdx.x;   // 0..16383
    const int dir = idx >> 13;
    const int bi  = idx & 8191;
    const int b   = bi >> 9;
    const int i   = bi & 511;

    const float* u0 = U   + (size_t)b * NDIM + dir * 1536 + i;
    const float* x0 = Xin + (size_t)b * DIN  + dir * 512  + i;
    float*       h0 = Xout + (size_t)b * DIN + dir * 512  + i;
    const int ustep = BATCH * NDIM;   // 49152
    const int xstep = BATCH * DIN;    // 16384

    float c = 0.f;
    if (dir == 0) {
        #pragma unroll 8
        for (int l = 0; l < LSEQ; l++) {
            const float* up = u0 + (size_t)l * ustep;
            float xt = __ldg(up);
            float f  = __ldg(up + 512);
            float r  = __ldg(up + 1024);
            float xp = __ldg(x0 + (size_t)l * xstep);
            c = f * c + (1.f - f) * xt;
            h0[(size_t)l * xstep] = r * tanh_fast(c) + (1.f - r) * xp;
        }
    } else {
        #pragma unroll 8
        for (int l = LSEQ - 1; l >= 0; l--) {
            const float* up = u0 + (size_t)l * ustep;
            float xt = __ldg(up);
            float f  = __ldg(up + 512);
            float r  = __ldg(up + 1024);
            float xp = __ldg(x0 + (size_t)l * xstep);
            c = f * c + (1.f - f) * xt;
            h0[(size_t)l * xstep] = r * tanh_fast(c) + (1.f - r) * xp;
        }
    }
    Cout[b * 1024 + dir * 512 + i] = c;
}

// ---------------------------------------------------------------------------
// Launch
// ---------------------------------------------------------------------------
extern "C" void kernel_launch(void* const* d_in, const int* in_sizes, int n_in,
                              void* d_out, int out_size) {
    const int*   tok = (const int*)d_in[0];
    const float* emb = (const float*)d_in[2];
    const float* Ws  = (const float*)d_in[3];
    const float* bs  = (const float*)d_in[4];
    float* out = (float*)d_out;

    float *x0, *x1, *u;
    cudaGetSymbolAddress((void**)&x0, g_x0);
    cudaGetSymbolAddress((void**)&x1, g_x1);
    cudaGetSymbolAddress((void**)&u,  g_u);

    gather_kernel<<<(MROWS * DIN / 4) / 256, 256>>>(tok, emb, x0);

    float* xcur = x0;
    float* xalt = x1;
    float* xout_base = out;
    float* hid_base  = out + (size_t)MROWS * DIN;

    dim3 ggrid(NDIM / 128, MROWS / 128);              // (24, 128)
    for (int l = 0; l < NLAY; l++) {
        const float* Wl = Ws + (size_t)l * KDIM * NDIM;
        const float* bl = bs + (size_t)l * 2048;
        gemm_tf32_kernel<<<ggrid, 256>>>(xcur, Wl, bl, u);

        float* xnext = (l == NLAY - 1) ? xout_base : xalt;
        scan_kernel<<<128, 128>>>(u, xcur, xnext, hid_base + (size_t)l * BATCH * DIN);

        xalt = xcur;
        xcur = xnext;
    }
}